// round 13
// baseline (speedup 1.0000x reference)
#include <cuda_runtime.h>
#include <cuda_fp16.h>

// NCA step via tensor cores: L1 = m16n8k16 f16 (packed D feeds L2 A directly),
// L2 = m16n8k16 f32-acc. 128-thread CTAs; each of 4 warps owns 4 M-tiles
// (64 pixels) to amortize fragment loads / loop overhead over 2x more MMAs.
// B=32, C=16, H=W=256, HID=128.

#define NB   32
#define NC   16
#define NH   256
#define NW   256
#define HID  128
#define HW   (NH * NW)

#define TLX  16
#define TLY  16
#define NPIX (TLX * TLY)
#define HSX  (TLX + 2)
#define HSY  (TLY + 2)
#define YSTW 28            // Y row stride in u32 words

__device__ float    g_ch3[NB * HW];
__device__ unsigned g_w1p[16 * 3 * 64];   // 3072 f16x2 words (B-frag layout, L1)
__device__ unsigned g_w2p[8 * 2 * 64];    // 1024 f16x2 words (B-frag layout, L2)
__device__ unsigned g_b1p[64];            // packed bias pairs

// smem layout (4B words)
#define SM_W1  0                          // 3072
#define SM_W2  (SM_W1 + 3072)             // 1024
#define SM_B1P (SM_W2 + 1024)             // 64
#define SM_UR  (SM_B1P + 64)              // 256
#define SM_XS  (SM_UR + 256)              // 5184
#define SM_YS  (SM_XS + HSY * HSX * NC)   // 7168
#define SM_WORDS (SM_YS + NPIX * YSTW)
#define SM_BYTES (SM_WORDS * 4)

__device__ __forceinline__ unsigned pk16(float lo, float hi) {
    __half2 h = __floats2half2_rn(lo, hi);
    return *(unsigned*)&h;
}
__device__ __forceinline__ unsigned relu2(unsigned v) {
    __half2 z = __float2half2_rn(0.f);
    __half2 r = __hmax2(*(__half2*)&v, z);
    return *(unsigned*)&r;
}

__device__ __forceinline__ void mma16h(unsigned c[2], const unsigned a[4],
                                       unsigned b0, unsigned b1) {
    asm volatile(
        "mma.sync.aligned.m16n8k16.row.col.f16.f16.f16.f16 "
        "{%0,%1}, {%2,%3,%4,%5}, {%6,%7}, {%0,%1};"
        : "+r"(c[0]), "+r"(c[1])
        : "r"(a[0]), "r"(a[1]), "r"(a[2]), "r"(a[3]), "r"(b0), "r"(b1));
}
__device__ __forceinline__ void mma16f(float c[4], const unsigned a[4],
                                       unsigned b0, unsigned b1) {
    asm volatile(
        "mma.sync.aligned.m16n8k16.row.col.f32.f16.f16.f32 "
        "{%0,%1,%2,%3}, {%4,%5,%6,%7}, {%8,%9}, {%0,%1,%2,%3};"
        : "+f"(c[0]), "+f"(c[1]), "+f"(c[2]), "+f"(c[3])
        : "r"(a[0]), "r"(a[1]), "r"(a[2]), "r"(a[3]), "r"(b0), "r"(b1));
}

// ---- prep: fragment-ready f16x2 weight packing (identity hidden perm) ----
__global__ void nca_prep(const float* __restrict__ w1, const float* __restrict__ b1,
                         const float* __restrict__ w2) {
    int i = blockIdx.x * 256 + threadIdx.x;
    if (i < 3072) {
        int r = i & 1, lane = (i >> 1) & 31;
        int kg2 = (i >> 6) % 3, g = i / 192;
        int t4 = lane & 3, q = lane >> 2;
        int h  = 8 * g + q;
        int f0 = 16 * kg2 + 2 * t4 + 8 * r;
        g_w1p[i] = pk16(w1[h * 48 + f0], w1[h * 48 + f0 + 1]);
    }
    int j = i - 3072;
    if (j >= 0 && j < 1024) {
        int r = j & 1, lane = (j >> 1) & 31;
        int ng = (j >> 6) & 1, p = j >> 7;
        int t4 = lane & 3, q = lane >> 2;
        int o  = q + 8 * ng;
        int h0 = 16 * p + 8 * r + 2 * t4;
        g_w2p[j] = pk16(w2[o * HID + h0], w2[o * HID + h0 + 1]);
    }
    int k = i - 4096;
    if (k >= 0 && k < 64) {
        int g = k >> 2, t4 = k & 3;
        g_b1p[k] = pk16(b1[8 * g + 2 * t4], b1[8 * g + 2 * t4 + 1]);
    }
}

extern __shared__ float smem[];

__global__ __launch_bounds__(128, 3)
void nca_main(const float* __restrict__ x, const float* __restrict__ ur,
              float* __restrict__ out) {
    const int b   = blockIdx.z;
    const int ty0 = blockIdx.y * TLY;
    const int tx0 = blockIdx.x * TLX;
    const int tid = threadIdx.x;   // 0..127

    unsigned* w1s  = (unsigned*)(smem + SM_W1);
    unsigned* w2s  = (unsigned*)(smem + SM_W2);
    unsigned* b1ps = (unsigned*)(smem + SM_B1P);
    float*    urs  = smem + SM_UR;
    float*    xs   = smem + SM_XS;
    unsigned* ysw  = (unsigned*)(smem + SM_YS);

    // ---- stage packed weights ----
    {
        const uint4* s1 = (const uint4*)g_w1p;
        uint4*       d1 = (uint4*)w1s;
        #pragma unroll
        for (int i = tid; i < 3072 / 4; i += 128) d1[i] = s1[i];
        const uint4* s2 = (const uint4*)g_w2p;
        uint4*       d2p = (uint4*)w2s;
        #pragma unroll
        for (int i = tid; i < 1024 / 4; i += 128) d2p[i] = s2[i];
        if (tid < 64) b1ps[tid] = g_b1p[tid];
    }

    // ---- stage halo tile + pre-gated update mask ----
    {
        const float* xb = x + (size_t)b * NC * HW;
        for (int i = tid; i < NC * HSY * HSX; i += 128) {
            int c = i / (HSY * HSX);
            int rem = i - c * (HSY * HSX);
            int yy = rem / HSX, xx = rem - (rem / HSX) * HSX;
            int gy = ty0 + yy - 1, gx = tx0 + xx - 1;
            float v = 0.f;
            if (gy >= 0 && gy < NH && gx >= 0 && gx < NW)
                v = xb[c * HW + gy * NW + gx];
            xs[i] = v;
        }
        #pragma unroll
        for (int i = tid; i < NPIX; i += 128) {
            int py = i / TLX, px = i % TLX;
            urs[i] = (ur[(size_t)b * HW + (ty0 + py) * NW + (tx0 + px)] <= 0.5f)
                     ? 1.f : 0.f;
        }
    }
    __syncthreads();

    // ---- perception -> f16x2 Y rows (2 pixels per thread) ----
    #pragma unroll
    for (int pp = 0; pp < 2; ++pp) {
        int pix = tid + 128 * pp;
        int py = pix / TLX, px = pix % TLX;
        unsigned* yr = ysw + pix * YSTW;
        float pend = 0.f;
        #pragma unroll
        for (int c = 0; c < NC; ++c) {
            const float* p = xs + c * (HSY * HSX) + py * HSX + px;
            float a00 = p[0],        a01 = p[1],           a02 = p[2];
            float a10 = p[HSX],      a11 = p[HSX + 1],     a12 = p[HSX + 2];
            float a20 = p[2 * HSX],  a21 = p[2 * HSX + 1], a22 = p[2 * HSX + 2];
            float sx = (a02 - a00 + 2.f * (a12 - a10) + a22 - a20) * 0.125f;
            float sy = (a20 - a00 + 2.f * (a21 - a01) + a22 - a02) * 0.125f;
            if ((c & 1) == 0) {
                yr[(3 * c) / 2] = pk16(a11, sx);
                pend = sy;
            } else {
                yr[(3 * c - 1) / 2] = pk16(pend, a11);
                yr[(3 * c + 1) / 2] = pk16(sx, sy);
            }
        }
    }
    __syncthreads();

    // ---- MLP on tensor cores: warp w owns pixel rows 4w..4w+3 ----
    const int w    = tid >> 5;
    const int lane = tid & 31;
    const int qid  = lane >> 2;
    const int r4   = lane & 3;

    unsigned ya[4][3][4];
    #pragma unroll
    for (int t = 0; t < 4; ++t) {
        int p0 = (4 * w + t) * TLX + qid;
        const unsigned* y0 = ysw + p0 * YSTW;
        const unsigned* y1 = ysw + (p0 + 8) * YSTW;
        #pragma unroll
        for (int kg = 0; kg < 3; ++kg) {
            ya[t][kg][0] = y0[8 * kg + r4];
            ya[t][kg][1] = y1[8 * kg + r4];
            ya[t][kg][2] = y0[8 * kg + r4 + 4];
            ya[t][kg][3] = y1[8 * kg + r4 + 4];
        }
    }

    float d2[4][2][4];
    #pragma unroll
    for (int t = 0; t < 4; ++t)
        #pragma unroll
        for (int n = 0; n < 2; ++n)
            #pragma unroll
            for (int e = 0; e < 4; ++e) d2[t][n][e] = 0.f;

    #pragma unroll 4
    for (int p = 0; p < 8; ++p) {
        unsigned h[4][4];
        #pragma unroll
        for (int gg = 0; gg < 2; ++gg) {
            int g = 2 * p + gg;
            unsigned bias = b1ps[4 * g + r4];
            unsigned c[4][2];
            #pragma unroll
            for (int t = 0; t < 4; ++t) { c[t][0] = bias; c[t][1] = bias; }
            const uint2* w1g = (const uint2*)w1s + (g * 3) * 32 + lane;
            #pragma unroll
            for (int kg = 0; kg < 3; ++kg) {
                uint2 bb = w1g[kg * 32];
                #pragma unroll
                for (int t = 0; t < 4; ++t)
                    mma16h(c[t], ya[t][kg], bb.x, bb.y);
            }
            #pragma unroll
            for (int t = 0; t < 4; ++t) {
                h[t][2 * gg + 0] = relu2(c[t][0]);
                h[t][2 * gg + 1] = relu2(c[t][1]);
            }
        }
        const uint2* w2g = (const uint2*)w2s + (p * 2) * 32 + lane;
        #pragma unroll
        for (int ng = 0; ng < 2; ++ng) {
            uint2 bb = w2g[ng * 32];
            #pragma unroll
            for (int t = 0; t < 4; ++t)
                mma16f(d2[t][ng], h[t], bb.x, bb.y);
        }
    }

    // ---- epilogue: x + dx*update (exact fp32 x from xs) ----
    #pragma unroll
    for (int t = 0; t < 4; ++t) {
        int py = 4 * w + t;
        int gy = ty0 + py;
        int p0 = py * TLX + qid;
        float u0 = urs[p0];
        float u1 = urs[p0 + 8];
        int gx0 = tx0 + qid, gx1 = gx0 + 8;
        float* ob = out + (size_t)b * NC * HW + gy * NW;
        #pragma unroll
        for (int ng = 0; ng < 2; ++ng) {
            #pragma unroll
            for (int bq = 0; bq < 2; ++bq) {
                int ch = 8 * ng + 2 * r4 + bq;
                const float* xc = xs + ch * (HSY * HSX) + (py + 1) * HSX + 1;
                float v0 = fmaf(d2[t][ng][bq],     u0, xc[qid]);
                float v1 = fmaf(d2[t][ng][bq + 2], u1, xc[qid + 8]);
                ob[(size_t)ch * HW + gx0] = v0;
                ob[(size_t)ch * HW + gx1] = v1;
                if (ch == 3) {
                    g_ch3[(size_t)b * HW + gy * NW + gx0] = v0;
                    g_ch3[(size_t)b * HW + gy * NW + gx1] = v1;
                }
            }
        }
    }
}

// mask: 4 pixels/thread, shared column maxes
__global__ void nca_mask(const float* __restrict__ x, float* __restrict__ out) {
    int idx = blockIdx.x * blockDim.x + threadIdx.x;
    if (idx >= NB * HW / 4) return;
    int b = idx / (HW / 4);
    int r = idx - b * (HW / 4);
    int i  = r / (NW / 4);
    int j0 = (r - i * (NW / 4)) * 4;

    const float* x3 = x + ((size_t)b * NC + 3) * HW;
    const float* n3 = g_ch3 + (size_t)b * HW;

    float cm0[6], cm1[6];
    #pragma unroll
    for (int k = 0; k < 6; ++k) {
        int jj = j0 - 1 + k;
        float a = -1e30f, c = -1e30f;
        if (jj >= 0 && jj < NW) {
            #pragma unroll
            for (int dy = -1; dy <= 1; ++dy) {
                int yy = i + dy;
                if (yy < 0 || yy >= NH) continue;
                a = fmaxf(a, x3[yy * NW + jj]);
                c = fmaxf(c, n3[yy * NW + jj]);
            }
        }
        cm0[k] = a; cm1[k] = c;
    }
    #pragma unroll
    for (int q = 0; q < 4; ++q) {
        float m0 = fmaxf(fmaxf(cm0[q], cm0[q + 1]), cm0[q + 2]);
        float m1 = fmaxf(fmaxf(cm1[q], cm1[q + 1]), cm1[q + 2]);
        if (!((m0 > 0.1f) && (m1 > 0.1f))) {
            float* ob = out + (size_t)b * NC * HW + i * NW + j0 + q;
            #pragma unroll
            for (int c = 0; c < NC; ++c) ob[(size_t)c * HW] = 0.f;
        }
    }
}

extern "C" void kernel_launch(void* const* d_in, const int* in_sizes, int n_in,
                              void* d_out, int out_size) {
    const float* x  = (const float*)d_in[0];
    const float* ur = (const float*)d_in[1];
    const float* w1 = (const float*)d_in[2];
    const float* b1 = (const float*)d_in[3];
    const float* w2 = (const float*)d_in[4];
    float* out = (float*)d_out;

    cudaFuncSetAttribute(nca_main, cudaFuncAttributeMaxDynamicSharedMemorySize, SM_BYTES);

    nca_prep<<<17, 256>>>(w1, b1, w2);

    dim3 grid(NW / TLX, NH / TLY, NB);
    nca_main<<<grid, 128, SM_BYTES>>>(x, ur, out);

    nca_mask<<<(NB * HW / 4 + 255) / 256, 256>>>(x, out);
}

// round 14
// speedup vs baseline: 1.1760x; 1.1760x over previous
#include <cuda_runtime.h>
#include <cuda_fp16.h>

// NCA step via tensor cores: L1 = m16n8k16 f16 (packed D feeds L2 A directly),
// L2 = m16n8k16 f32-acc. 256-thread CTAs, 8 warps x 2 M-tiles (round-9
// structure) + ldmatrix.x4 A-fragment loads. B=32, C=16, H=W=256, HID=128.

#define NB   32
#define NC   16
#define NH   256
#define NW   256
#define HID  128
#define HW   (NH * NW)

#define TLX  16
#define TLY  16
#define NPIX (TLX * TLY)
#define HSX  (TLX + 2)
#define HSY  (TLY + 2)
#define YSTW 28            // Y row stride in u32 words (112 B, 16B-aligned)

__device__ float    g_ch3[NB * HW];
__device__ unsigned g_w1p[16 * 3 * 64];   // 3072 f16x2 words (B-frag layout, L1)
__device__ unsigned g_w2p[8 * 2 * 64];    // 1024 f16x2 words (B-frag layout, L2)
__device__ unsigned g_b1p[64];            // packed bias pairs

// smem layout (4B words)
#define SM_W1  0                          // 3072
#define SM_W2  (SM_W1 + 3072)             // 1024
#define SM_B1P (SM_W2 + 1024)             // 64
#define SM_UR  (SM_B1P + 64)              // 256
#define SM_XS  (SM_UR + 256)              // 5184
#define SM_YS  (SM_XS + HSY * HSX * NC)   // 7168
#define SM_WORDS (SM_YS + NPIX * YSTW)
#define SM_BYTES (SM_WORDS * 4)

__device__ __forceinline__ unsigned pk16(float lo, float hi) {
    __half2 h = __floats2half2_rn(lo, hi);
    return *(unsigned*)&h;
}
__device__ __forceinline__ unsigned relu2(unsigned v) {
    __half2 z = __float2half2_rn(0.f);
    __half2 r = __hmax2(*(__half2*)&v, z);
    return *(unsigned*)&r;
}

__device__ __forceinline__ void mma16h(unsigned c[2], const unsigned a[4],
                                       unsigned b0, unsigned b1) {
    asm volatile(
        "mma.sync.aligned.m16n8k16.row.col.f16.f16.f16.f16 "
        "{%0,%1}, {%2,%3,%4,%5}, {%6,%7}, {%0,%1};"
        : "+r"(c[0]), "+r"(c[1])
        : "r"(a[0]), "r"(a[1]), "r"(a[2]), "r"(a[3]), "r"(b0), "r"(b1));
}
__device__ __forceinline__ void mma16f(float c[4], const unsigned a[4],
                                       unsigned b0, unsigned b1) {
    asm volatile(
        "mma.sync.aligned.m16n8k16.row.col.f32.f16.f16.f32 "
        "{%0,%1,%2,%3}, {%4,%5,%6,%7}, {%8,%9}, {%0,%1,%2,%3};"
        : "+f"(c[0]), "+f"(c[1]), "+f"(c[2]), "+f"(c[3])
        : "r"(a[0]), "r"(a[1]), "r"(a[2]), "r"(a[3]), "r"(b0), "r"(b1));
}
__device__ __forceinline__ void ldsm4(unsigned r[4], unsigned addr) {
    asm volatile("ldmatrix.sync.aligned.m8n8.x4.shared.b16 {%0,%1,%2,%3}, [%4];"
                 : "=r"(r[0]), "=r"(r[1]), "=r"(r[2]), "=r"(r[3]) : "r"(addr));
}
__device__ __forceinline__ unsigned smem_u32(const void* p) {
    unsigned a;
    asm("{ .reg .u64 t; cvta.to.shared.u64 t, %1; cvt.u32.u64 %0, t; }"
        : "=r"(a) : "l"(p));
    return a;
}

// ---- prep: fragment-ready f16x2 weight packing (identity hidden perm) ----
__global__ void nca_prep(const float* __restrict__ w1, const float* __restrict__ b1,
                         const float* __restrict__ w2) {
    int i = blockIdx.x * 256 + threadIdx.x;
    if (i < 3072) {
        int r = i & 1, lane = (i >> 1) & 31;
        int kg2 = (i >> 6) % 3, g = i / 192;
        int t4 = lane & 3, q = lane >> 2;
        int h  = 8 * g + q;
        int f0 = 16 * kg2 + 2 * t4 + 8 * r;
        g_w1p[i] = pk16(w1[h * 48 + f0], w1[h * 48 + f0 + 1]);
    }
    int j = i - 3072;
    if (j >= 0 && j < 1024) {
        int r = j & 1, lane = (j >> 1) & 31;
        int ng = (j >> 6) & 1, p = j >> 7;
        int t4 = lane & 3, q = lane >> 2;
        int o  = q + 8 * ng;
        int h0 = 16 * p + 8 * r + 2 * t4;
        g_w2p[j] = pk16(w2[o * HID + h0], w2[o * HID + h0 + 1]);
    }
    int k = i - 4096;
    if (k >= 0 && k < 64) {
        int g = k >> 2, t4 = k & 3;
        g_b1p[k] = pk16(b1[8 * g + 2 * t4], b1[8 * g + 2 * t4 + 1]);
    }
}

extern __shared__ float smem[];

__global__ __launch_bounds__(256, 3)
void nca_main(const float* __restrict__ x, const float* __restrict__ ur,
              float* __restrict__ out) {
    const int b   = blockIdx.z;
    const int ty0 = blockIdx.y * TLY;
    const int tx0 = blockIdx.x * TLX;
    const int tid = threadIdx.x;

    unsigned* w1s  = (unsigned*)(smem + SM_W1);
    unsigned* w2s  = (unsigned*)(smem + SM_W2);
    unsigned* b1ps = (unsigned*)(smem + SM_B1P);
    float*    urs  = smem + SM_UR;
    float*    xs   = smem + SM_XS;
    unsigned* ysw  = (unsigned*)(smem + SM_YS);

    // ---- stage packed weights ----
    {
        const uint4* s1 = (const uint4*)g_w1p;
        uint4*       d1 = (uint4*)w1s;
        #pragma unroll
        for (int i = tid; i < 3072 / 4; i += 256) d1[i] = s1[i];
        const uint4* s2 = (const uint4*)g_w2p;
        uint4*       d2p = (uint4*)w2s;
        if (tid < 1024 / 4) d2p[tid] = s2[tid];
        if (tid < 64) b1ps[tid] = g_b1p[tid];
    }

    // ---- stage halo tile + pre-gated update mask ----
    {
        const float* xb = x + (size_t)b * NC * HW;
        for (int i = tid; i < NC * HSY * HSX; i += 256) {
            int c = i / (HSY * HSX);
            int rem = i - c * (HSY * HSX);
            int yy = rem / HSX, xx = rem - (rem / HSX) * HSX;
            int gy = ty0 + yy - 1, gx = tx0 + xx - 1;
            float v = 0.f;
            if (gy >= 0 && gy < NH && gx >= 0 && gx < NW)
                v = xb[c * HW + gy * NW + gx];
            xs[i] = v;
        }
        int py = tid / TLX, px = tid % TLX;
        urs[tid] = (ur[(size_t)b * HW + (ty0 + py) * NW + (tx0 + px)] <= 0.5f)
                   ? 1.f : 0.f;
    }
    __syncthreads();

    // ---- perception -> f16x2 Y rows (48 halves = 24 words) ----
    {
        int py = tid / TLX, px = tid % TLX;
        unsigned* yr = ysw + tid * YSTW;
        float pend = 0.f;
        #pragma unroll
        for (int c = 0; c < NC; ++c) {
            const float* p = xs + c * (HSY * HSX) + py * HSX + px;
            float a00 = p[0],        a01 = p[1],           a02 = p[2];
            float a10 = p[HSX],      a11 = p[HSX + 1],     a12 = p[HSX + 2];
            float a20 = p[2 * HSX],  a21 = p[2 * HSX + 1], a22 = p[2 * HSX + 2];
            float sx = (a02 - a00 + 2.f * (a12 - a10) + a22 - a20) * 0.125f;
            float sy = (a20 - a00 + 2.f * (a21 - a01) + a22 - a02) * 0.125f;
            if ((c & 1) == 0) {
                yr[(3 * c) / 2] = pk16(a11, sx);
                pend = sy;
            } else {
                yr[(3 * c - 1) / 2] = pk16(pend, a11);
                yr[(3 * c + 1) / 2] = pk16(sx, sy);
            }
        }
    }
    __syncthreads();

    // ---- MLP on tensor cores ----
    const int w    = tid >> 5;
    const int lane = tid & 31;
    const int qid  = lane >> 2;
    const int r4   = lane & 3;

    // A fragments via ldmatrix.x4: canonical lane->row map.
    unsigned ya[2][3][4];
    {
        const unsigned ysb = smem_u32(ysw);
        const int row_in_tile = (lane & 7) + ((lane >> 3) & 1) * 8;
        const unsigned koff = (unsigned)(lane >> 4) * 16u;
        #pragma unroll
        for (int t = 0; t < 2; ++t) {
            int pix = (2 * w + t) * TLX + row_in_tile;
            unsigned base = ysb + (unsigned)pix * (YSTW * 4) + koff;
            #pragma unroll
            for (int kg = 0; kg < 3; ++kg)
                ldsm4(ya[t][kg], base + (unsigned)kg * 32u);
        }
    }

    float d2[2][2][4];
    #pragma unroll
    for (int t = 0; t < 2; ++t)
        #pragma unroll
        for (int n = 0; n < 2; ++n)
            #pragma unroll
            for (int e = 0; e < 4; ++e) d2[t][n][e] = 0.f;

    #pragma unroll
    for (int p = 0; p < 8; ++p) {
        unsigned h0[4], h1[4];
        #pragma unroll
        for (int gg = 0; gg < 2; ++gg) {
            int g = 2 * p + gg;
            unsigned bias = b1ps[4 * g + r4];
            unsigned c0[2] = {bias, bias};
            unsigned c1[2] = {bias, bias};
            const uint2* w1g = (const uint2*)w1s + (g * 3) * 32 + lane;
            #pragma unroll
            for (int kg = 0; kg < 3; ++kg) {
                uint2 bb = w1g[kg * 32];
                mma16h(c0, ya[0][kg], bb.x, bb.y);
                mma16h(c1, ya[1][kg], bb.x, bb.y);
            }
            h0[2 * gg + 0] = relu2(c0[0]);
            h0[2 * gg + 1] = relu2(c0[1]);
            h1[2 * gg + 0] = relu2(c1[0]);
            h1[2 * gg + 1] = relu2(c1[1]);
        }
        const uint2* w2g = (const uint2*)w2s + (p * 2) * 32 + lane;
        #pragma unroll
        for (int ng = 0; ng < 2; ++ng) {
            uint2 bb = w2g[ng * 32];
            mma16f(d2[0][ng], h0, bb.x, bb.y);
            mma16f(d2[1][ng], h1, bb.x, bb.y);
        }
    }

    // ---- epilogue: x + dx*update (exact fp32 x from xs) ----
    #pragma unroll
    for (int t = 0; t < 2; ++t) {
        int py = 2 * w + t;
        int gy = ty0 + py;
        int p0 = py * TLX + qid;
        float u0 = urs[p0];
        float u1 = urs[p0 + 8];
        int gx0 = tx0 + qid, gx1 = gx0 + 8;
        float* ob = out + (size_t)b * NC * HW + gy * NW;
        #pragma unroll
        for (int ng = 0; ng < 2; ++ng) {
            #pragma unroll
            for (int bq = 0; bq < 2; ++bq) {
                int ch = 8 * ng + 2 * r4 + bq;
                const float* xc = xs + ch * (HSY * HSX) + (py + 1) * HSX + 1;
                float v0 = fmaf(d2[t][ng][bq],     u0, xc[qid]);
                float v1 = fmaf(d2[t][ng][bq + 2], u1, xc[qid + 8]);
                ob[(size_t)ch * HW + gx0] = v0;
                ob[(size_t)ch * HW + gx1] = v1;
                if (ch == 3) {
                    g_ch3[(size_t)b * HW + gy * NW + gx0] = v0;
                    g_ch3[(size_t)b * HW + gy * NW + gx1] = v1;
                }
            }
        }
    }
}

// mask: 4 pixels/thread, shared column maxes
__global__ void nca_mask(const float* __restrict__ x, float* __restrict__ out) {
    int idx = blockIdx.x * blockDim.x + threadIdx.x;
    if (idx >= NB * HW / 4) return;
    int b = idx / (HW / 4);
    int r = idx - b * (HW / 4);
    int i  = r / (NW / 4);
    int j0 = (r - i * (NW / 4)) * 4;

    const float* x3 = x + ((size_t)b * NC + 3) * HW;
    const float* n3 = g_ch3 + (size_t)b * HW;

    float cm0[6], cm1[6];
    #pragma unroll
    for (int k = 0; k < 6; ++k) {
        int jj = j0 - 1 + k;
        float a = -1e30f, c = -1e30f;
        if (jj >= 0 && jj < NW) {
            #pragma unroll
            for (int dy = -1; dy <= 1; ++dy) {
                int yy = i + dy;
                if (yy < 0 || yy >= NH) continue;
                a = fmaxf(a, x3[yy * NW + jj]);
                c = fmaxf(c, n3[yy * NW + jj]);
            }
        }
        cm0[k] = a; cm1[k] = c;
    }
    #pragma unroll
    for (int q = 0; q < 4; ++q) {
        float m0 = fmaxf(fmaxf(cm0[q], cm0[q + 1]), cm0[q + 2]);
        float m1 = fmaxf(fmaxf(cm1[q], cm1[q + 1]), cm1[q + 2]);
        if (!((m0 > 0.1f) && (m1 > 0.1f))) {
            float* ob = out + (size_t)b * NC * HW + i * NW + j0 + q;
            #pragma unroll
            for (int c = 0; c < NC; ++c) ob[(size_t)c * HW] = 0.f;
        }
    }
}

extern "C" void kernel_launch(void* const* d_in, const int* in_sizes, int n_in,
                              void* d_out, int out_size) {
    const float* x  = (const float*)d_in[0];
    const float* ur = (const float*)d_in[1];
    const float* w1 = (const float*)d_in[2];
    const float* b1 = (const float*)d_in[3];
    const float* w2 = (const float*)d_in[4];
    float* out = (float*)d_out;

    cudaFuncSetAttribute(nca_main, cudaFuncAttributeMaxDynamicSharedMemorySize, SM_BYTES);

    nca_prep<<<17, 256>>>(w1, b1, w2);

    dim3 grid(NW / TLX, NH / TLY, NB);
    nca_main<<<grid, 256, SM_BYTES>>>(x, ur, out);

    nca_mask<<<(NB * HW / 4 + 255) / 256, 256>>>(x, out);
}